// round 16
// baseline (speedup 1.0000x reference)
#include <cuda_runtime.h>
#include <cuda_fp16.h>
#include <math.h>
#include <stdint.h>

#define SQ   2048
#define DIM  512
#define NH   8
#define HDIM 64
#define NB   4
#define WIN  64
#define MROWS (NB * SQ)        // 8192
#define QKVD (3 * DIM)         // 1536
#define FFD  2048
#define GCH  16                // key chunks for query-0 global attention

// ---------------- scratch ----------------------------------------------------
__device__ __half g_a   [(size_t)MROWS * DIM];
__device__ __half g_qkvh[(size_t)MROWS * QKVD];
__device__ __half g_o   [(size_t)MROWS * DIM];
__device__ float  g_x1  [(size_t)MROWS * DIM];
__device__ __half g_f   [(size_t)MROWS * DIM];
__device__ __half g_h   [(size_t)MROWS * FFD];
__device__ __half g_wqkv[(size_t)QKVD * DIM];
__device__ __half g_wo  [(size_t)DIM * DIM];
__device__ __half g_w1h [(size_t)FFD * DIM];
__device__ __half g_w2h [(size_t)DIM * FFD];
// split-softmax partials for query-0 global attention
__device__ float  g_pm  [NB * NH * GCH];
__device__ float  g_ps  [NB * NH * GCH];
__device__ float  g_pa  [NB * NH * GCH * HDIM];

// ---------------- helpers ----------------------------------------------------
__device__ __forceinline__ uint32_t smem_u32(const void* p) {
    return (uint32_t)__cvta_generic_to_shared(p);
}
__device__ __forceinline__ void ldsm_x4(uint32_t* r, uint32_t addr) {
    asm volatile("ldmatrix.sync.aligned.m8n8.x4.shared.b16 {%0,%1,%2,%3}, [%4];\n"
        : "=r"(r[0]), "=r"(r[1]), "=r"(r[2]), "=r"(r[3]) : "r"(addr));
}
__device__ __forceinline__ void ldsm_x2(uint32_t* r, uint32_t addr) {
    asm volatile("ldmatrix.sync.aligned.m8n8.x2.shared.b16 {%0,%1}, [%2];\n"
        : "=r"(r[0]), "=r"(r[1]) : "r"(addr));
}
__device__ __forceinline__ void ldsm_x2_trans(uint32_t* r, uint32_t addr) {
    asm volatile("ldmatrix.sync.aligned.m8n8.x2.trans.shared.b16 {%0,%1}, [%2];\n"
        : "=r"(r[0]), "=r"(r[1]) : "r"(addr));
}
__device__ __forceinline__ void mma16816(float* c, const uint32_t* a, const uint32_t* b) {
    asm volatile(
        "mma.sync.aligned.m16n8k16.row.col.f32.f16.f16.f32 "
        "{%0,%1,%2,%3},{%4,%5,%6,%7},{%8,%9},{%0,%1,%2,%3};\n"
        : "+f"(c[0]), "+f"(c[1]), "+f"(c[2]), "+f"(c[3])
        : "r"(a[0]), "r"(a[1]), "r"(a[2]), "r"(a[3]), "r"(b[0]), "r"(b[1]));
}
__device__ __forceinline__ void cp16cg(uint32_t saddr, const void* g) {
    asm volatile("cp.async.cg.shared.global [%0], [%1], 16;\n" :: "r"(saddr), "l"(g));
}
#define CP_COMMIT() asm volatile("cp.async.commit_group;\n" ::: "memory")
#define CP_WAIT2()  asm volatile("cp.async.wait_group 2;\n" ::: "memory")
#define CP_WAIT0()  asm volatile("cp.async.wait_group 0;\n" ::: "memory")

__device__ __forceinline__ float gelu_exact(float v) {
    return 0.5f * v * (1.0f + erff(v * 0.70710678118654752f));
}
__device__ __forceinline__ void st2(float* p, float a, float b) { p[0] = a; p[1] = b; }
__device__ __forceinline__ void st2(__half* p, float a, float b) {
    *(__half2*)p = __floats2half2_rn(a, b);
}

// ---------------- fused fp32 -> fp16 weight convert --------------------------
#define N1 (QKVD * DIM)
#define N2 (DIM * DIM)
#define N3 (FFD * DIM)
#define N4 (DIM * FFD)
__global__ void f2h_all_kernel(const float* __restrict__ s1, __half* __restrict__ d1,
                               const float* __restrict__ s2, __half* __restrict__ d2,
                               const float* __restrict__ s3, __half* __restrict__ d3,
                               const float* __restrict__ s4, __half* __restrict__ d4) {
    int i = (blockIdx.x * blockDim.x + threadIdx.x) * 4;
    const float* s; __half* d;
    if (i < N1)                     { s = s1; d = d1; }
    else if ((i -= N1) < N2)        { s = s2; d = d2; }
    else if ((i -= N2) < N3)        { s = s3; d = d3; }
    else if ((i -= N3) < N4)        { s = s4; d = d4; }
    else return;
    float4 v = *(const float4*)(s + i);
    ((__half2*)d)[i / 2]     = __floats2half2_rn(v.x, v.y);
    ((__half2*)d)[i / 2 + 1] = __floats2half2_rn(v.z, v.w);
}

// ---------------- LayerNorm: 2 rows per 256-thread block ---------------------
__global__ __launch_bounds__(256)
void ln_kernel(const float* __restrict__ x, const float* __restrict__ g,
               const float* __restrict__ bb, __half* __restrict__ out) {
    const int half = threadIdx.x >> 7;
    const int tid  = threadIdx.x & 127;
    const int row  = blockIdx.x * 2 + half;
    const float4* xr = (const float4*)(x + (size_t)row * DIM);
    float4 v = xr[tid];
    float s  = v.x + v.y + v.z + v.w;
    float ss = v.x*v.x + v.y*v.y + v.z*v.z + v.w*v.w;
    #pragma unroll
    for (int o = 16; o > 0; o >>= 1) {
        s  += __shfl_xor_sync(0xffffffffu, s,  o);
        ss += __shfl_xor_sync(0xffffffffu, ss, o);
    }
    __shared__ float as_[2][4], ass_[2][4];
    if ((tid & 31) == 0) { as_[half][tid >> 5] = s; ass_[half][tid >> 5] = ss; }
    __syncthreads();
    s  = as_[half][0] + as_[half][1] + as_[half][2] + as_[half][3];
    ss = ass_[half][0] + ass_[half][1] + ass_[half][2] + ass_[half][3];
    const float mean = s * (1.0f / DIM);
    const float var  = ss * (1.0f / DIM) - mean * mean;
    const float inv  = rsqrtf(var + 1e-5f);
    float4 gv = ((const float4*)g)[tid];
    float4 bv = ((const float4*)bb)[tid];
    float r0 = (v.x - mean) * inv * gv.x + bv.x;
    float r1 = (v.y - mean) * inv * gv.y + bv.y;
    float r2 = (v.z - mean) * inv * gv.z + bv.z;
    float r3 = (v.w - mean) * inv * gv.w + bv.w;
    __half2* orow = (__half2*)(out + (size_t)row * DIM);
    orow[2 * tid]     = __floats2half2_rn(r0, r1);
    orow[2 * tid + 1] = __floats2half2_rn(r2, r3);
}

// ---------------- fp16 tensor-core GEMM: 4-stage pipeline --------------------
#define LDK 20           // smem words (half2) per 32-half row (16 + pad 4)
#define STGW (128 * LDK) // words per stage per operand
#define GEMM_SMEM (8 * STGW * 4)  // 4 stages x (A + B) = 80 KB

template <int EPI, typename OT>
__global__ __launch_bounds__(256)
void tgemm(const __half* __restrict__ A, const __half* __restrict__ W,
           const float* __restrict__ bias, const float* __restrict__ R,
           OT* __restrict__ C, int M, int N, int K) {
    extern __shared__ __align__(16) uint32_t dynsm[];
    uint32_t* As = dynsm;              // 4 * STGW
    uint32_t* Bs = dynsm + 4 * STGW;   // 4 * STGW

    const int tid  = threadIdx.x;
    const int warp = tid >> 5;
    const int lane = tid & 31;
    const int g    = lane >> 2;
    const int t4   = lane & 3;
    const int wm   = warp >> 2;
    const int wn   = warp & 3;

    const int bm = blockIdx.y * 128;
    const int bn = blockIdx.x * 128;

    const int lrow = tid >> 1;
    const __half* gA = A + (size_t)(bm + lrow) * K + (tid & 1) * 16;
    const __half* gB = W + (size_t)(bn + lrow) * K + (tid & 1) * 16;
    const uint32_t sA = smem_u32(As) + (lrow * LDK + (tid & 1) * 8) * 4;
    const uint32_t sB = smem_u32(Bs) + (lrow * LDK + (tid & 1) * 8) * 4;
    const int STGB = STGW * 4;         // stage stride in bytes

    const int l15 = lane & 15;
    const uint32_t aBase = smem_u32(As) +
        (((wm * 64 + l15) * LDK) + (lane >> 4) * 4) * 4;
    // paired-B ldsm.x4 base (R14 proven)
    const uint32_t bBase4 = smem_u32(Bs) +
        (((wn * 32 + (lane & 7)) * LDK) + ((lane >> 3) & 1) * 4) * 4
        + (lane >> 4) * (8 * LDK * 4);

    float acc[4][4][4];
    #pragma unroll
    for (int i = 0; i < 4; i++)
        #pragma unroll
        for (int j = 0; j < 4; j++)
            #pragma unroll
            for (int v = 0; v < 4; v++) acc[i][j][v] = 0.0f;

    const int NT = K / 32;             // >= 16 for our shapes
    // prologue: stages 0,1,2
    #pragma unroll
    for (int p = 0; p < 3; p++) {
        const int k0 = p * 32;
        cp16cg(sA + p * STGB, gA + k0); cp16cg(sA + p * STGB + 16, gA + k0 + 8);
        cp16cg(sB + p * STGB, gB + k0); cp16cg(sB + p * STGB + 16, gB + k0 + 8);
        CP_COMMIT();
    }

    for (int t = 0; t < NT; t++) {
        CP_WAIT2();          // stage t arrived (<=2 younger groups pending)
        __syncthreads();
        if (t + 3 < NT) {
            const int k0 = (t + 3) * 32;
            const int po = ((t + 3) & 3) * STGB;
            cp16cg(sA + po, gA + k0); cp16cg(sA + po + 16, gA + k0 + 8);
            cp16cg(sB + po, gB + k0); cp16cg(sB + po + 16, gB + k0 + 8);
        }
        CP_COMMIT();
        const int sb = (t & 3) * STGB;
        #pragma unroll
        for (int kk = 0; kk < 2; kk++) {
            uint32_t af[4][4], bf[4][2];
            #pragma unroll
            for (int mt = 0; mt < 4; mt++)
                ldsm_x4(af[mt], aBase + sb + mt * (16 * LDK * 4) + kk * 32);
            ldsm_x4(&bf[0][0], bBase4 + sb + kk * 32);
            ldsm_x4(&bf[2][0], bBase4 + sb + 16 * LDK * 4 + kk * 32);
            #pragma unroll
            for (int mt = 0; mt < 4; mt++)
                #pragma unroll
                for (int nt = 0; nt < 4; nt++)
                    mma16816(acc[mt][nt], af[mt], bf[nt]);
        }
    }

    #pragma unroll
    for (int mt = 0; mt < 4; mt++) {
        const int r0 = bm + wm * 64 + mt * 16 + g;
        const int r1 = r0 + 8;
        #pragma unroll
        for (int nt = 0; nt < 4; nt++) {
            const int col = bn + wn * 32 + nt * 8 + 2 * t4;
            const float b0 = bias[col], b1 = bias[col + 1];
            float v0 = acc[mt][nt][0] + b0;
            float v1 = acc[mt][nt][1] + b1;
            float v2 = acc[mt][nt][2] + b0;
            float v3 = acc[mt][nt][3] + b1;
            if (EPI == 1) {
                v0 = gelu_exact(v0); v1 = gelu_exact(v1);
                v2 = gelu_exact(v2); v3 = gelu_exact(v3);
            }
            if (EPI == 2) {
                float2 ra = *(const float2*)(R + (size_t)r0 * N + col);
                float2 rb = *(const float2*)(R + (size_t)r1 * N + col);
                v0 += ra.x; v1 += ra.y; v2 += rb.x; v3 += rb.y;
            }
            st2(C + (size_t)r0 * N + col, v0, v1);
            st2(C + (size_t)r1 * N + col, v2, v3);
        }
    }
}

// ---------------- Tiled attention (R15 proven, unchanged) --------------------
#define TQ    32
#define NKP   168
#define VROWS 176
#define LDAT  36
#define LDP   184
#define KJ_INVALID 0x40000000
#define ATTN_SMEM (((32 + NKP + VROWS) * LDAT) * 4 + 32 * LDP * 2 + 2 * 128 * 4 + NKP * 4 + 64)

__global__ __launch_bounds__(256)
void attn_tile_kernel(const __half* __restrict__ qkv,
                      const unsigned char* __restrict__ pad,
                      __half* __restrict__ o) {
    extern __shared__ __align__(16) uint32_t sm[];
    uint32_t* Qs  = sm;
    uint32_t* Ksm = Qs + 32 * LDAT;
    uint32_t* Vsm = Ksm + NKP * LDAT;
    __half*   Ps  = (__half*)(Vsm + VROWS * LDAT);
    float*    pmax = (float*)(Ps + 32 * LDP);
    float*    psum = pmax + 128;
    int*      kjs  = (int*)(psum + 128);

    const int q0 = blockIdx.x * TQ;
    const int h  = blockIdx.y;
    const int b  = blockIdx.z;
    const int tid  = threadIdx.x;
    const int warp = tid >> 5;
    const int lane = tid & 31;
    const int g    = lane >> 2;
    const int t4   = lane & 3;

    int ks = q0 - WIN; if (ks < 0) ks = 0;
    int ke = q0 + TQ - 1 + WIN; if (ke > SQ - 1) ke = SQ - 1;
    const int hasg = (ks > 0) ? 1 : 0;
    const int nk = ke - ks + 1 + hasg;
    const int ntmax = (nk + 7) >> 3;
    const int NTK = (nk + 15) >> 4;

    {
        const int qrow = tid >> 3, l8 = tid & 7;
        cp16cg(smem_u32(Qs) + (qrow * LDAT + l8 * 4) * 4,
               qkv + ((size_t)(b * SQ + q0 + qrow)) * QKVD + h * HDIM + l8 * 8);
    }
    {
        const int l8 = tid & 7;
        for (int j = tid >> 3; j < VROWS; j += 32) {
            if (j < nk) {
                const int kj = (hasg && j == 0) ? 0 : ks + j - hasg;
                const __half* base = qkv + ((size_t)(b * SQ + kj)) * QKVD;
                cp16cg(smem_u32(Ksm) + (j * LDAT + l8 * 4) * 4,
                       base + DIM + h * HDIM + l8 * 8);
                cp16cg(smem_u32(Vsm) + (j * LDAT + l8 * 4) * 4,
                       base + 2 * DIM + h * HDIM + l8 * 8);
                if (l8 == 0) kjs[j] = pad[b * SQ + kj] ? KJ_INVALID : kj;
            } else {
                uint4 z = {0u, 0u, 0u, 0u};
                *(uint4*)(Vsm + j * LDAT + l8 * 4) = z;
                if (l8 == 0 && j < NKP) kjs[j] = KJ_INVALID;
            }
        }
    }
    {
        const int row = tid >> 3;
        const int cc = ntmax * 8 + (tid & 7);
        if (cc < NTK * 16) Ps[row * LDP + cc] = __float2half(0.f);
    }
    CP_COMMIT();
    CP_WAIT0();
    __syncthreads();

    {
        const int mt = warp & 1;
        const int ng = warp >> 1;
        const int l15 = lane & 15;
        const uint32_t aAddr = smem_u32(Qs) +
            (((mt * 16 + l15) * LDAT) + (lane >> 4) * 4) * 4;
        uint32_t af[4][4];
        #pragma unroll
        for (int kk = 0; kk < 4; kk++) ldsm_x4(af[kk], aAddr + kk * 32);

        const uint32_t bAddr = smem_u32(Ksm) +
            (((l15 & 7) * LDAT) + (l15 >> 3) * 4) * 4;

        float cs[6][4];
        #pragma unroll
        for (int i = 0; i < 6; i++) {
            const int nt = ng + i * 4;
            cs[i][0] = cs[i][1] = cs[i][2] = cs[i][3] = 0.f;
            if (nt < ntmax) {
                #pragma unroll
                for (int kk = 0; kk < 4; kk++) {
                    uint32_t bf[2];
                    ldsm_x2(bf, bAddr + nt * (8 * LDAT * 4) + kk * 32);
                    mma16816(cs[i], af[kk], bf);
                }
            }
        }

        const int qg0 = q0 + mt * 16 + g;
        const int qg1 = qg0 + 8;
        float m0 = -1e30f, m1 = -1e30f;
        #pragma unroll
        for (int i = 0; i < 6; i++) {
            const int nt = ng + i * 4;
            if (nt < ntmax) {
                #pragma unroll
                for (int u = 0; u < 2; u++) {
                    const int col = nt * 8 + 2 * t4 + u;
                    const int kj = kjs[col];
                    const int d0 = kj - qg0;
                    const bool v0 = (kj == 0) || (d0 >= -WIN && d0 <= WIN);
                    float s0 = v0 ? cs[i][u] * 0.125f : -1e30f;
                    cs[i][u] = s0; m0 = fmaxf(m0, s0);
                    const int d1 = kj - qg1;
                    const bool v1 = (kj == 0) || (d1 >= -WIN && d1 <= WIN);
                    float s1 = v1 ? cs[i][u + 2] * 0.125f : -1e30f;
                    cs[i][u + 2] = s1; m1 = fmaxf(m1, s1);
                }
            }
        }
        m0 = fmaxf(m0, __shfl_xor_sync(0xffffffffu, m0, 1));
        m0 = fmaxf(m0, __shfl_xor_sync(0xffffffffu, m0, 2));
        m1 = fmaxf(m1, __shfl_xor_sync(0xffffffffu, m1, 1));
        m1 = fmaxf(m1, __shfl_xor_sync(0xffffffffu, m1, 2));
        const int r0 = mt * 16 + g, r1 = r0 + 8;
        if (t4 == 0) { pmax[r0 * 4 + ng] = m0; pmax[r1 * 4 + ng] = m1; }
        __syncthreads();
        const float M0 = fmaxf(fmaxf(pmax[r0 * 4], pmax[r0 * 4 + 1]),
                               fmaxf(pmax[r0 * 4 + 2], pmax[r0 * 4 + 3]));
        const float M1 = fmaxf(fmaxf(pmax[r1 * 4], pmax[r1 * 4 + 1]),
                               fmaxf(pmax[r1 * 4 + 2], pmax[r1 * 4 + 3]));

        float s0 = 0.f, s1 = 0.f;
        #pragma unroll
        for (int i = 0; i < 6; i++) {
            const int nt = ng + i * 4;
            if (nt < ntmax) {
                const int col = nt * 8 + 2 * t4;
                float e0 = __expf(cs[i][0] - M0);
                float e1 = __expf(cs[i][1] - M0);
                float e2 = __expf(cs[i][2] - M1);
                float e3 = __expf(cs[i][3] - M1);
                s0 += e0 + e1; s1 += e2 + e3;
                *(__half2*)(Ps + r0 * LDP + col) = __floats2half2_rn(e0, e1);
                *(__half2*)(Ps + r1 * LDP + col) = __floats2half2_rn(e2, e3);
            }
        }
        s0 += __shfl_xor_sync(0xffffffffu, s0, 1);
        s0 += __shfl_xor_sync(0xffffffffu, s0, 2);
        s1 += __shfl_xor_sync(0xffffffffu, s1, 1);
        s1 += __shfl_xor_sync(0xffffffffu, s1, 2);
        if (t4 == 0) { psum[r0 * 4 + ng] = s0; psum[r1 * 4 + ng] = s1; }
    }
    __syncthreads();

    {
        const int mt = warp >> 2;
        const int wn = warp & 3;
        const int l15 = lane & 15;
        float c[2][4];
        #pragma unroll
        for (int t = 0; t < 2; t++)
            #pragma unroll
            for (int v = 0; v < 4; v++) c[t][v] = 0.f;

        const uint32_t aBase = smem_u32(Ps) +
            (mt * 16 + l15) * (LDP * 2) + (lane >> 4) * 16;
        const uint32_t vBase = smem_u32(Vsm) + l15 * (LDAT * 4);
        for (int kk = 0; kk < NTK; kk++) {
            uint32_t a[4];
            ldsm_x4(a, aBase + kk * 32);
            #pragma unroll
            for (int t = 0; t < 2; t++) {
                const int nt = wn + t * 4;
                uint32_t bf[2];
                ldsm_x2_trans(bf, vBase + kk * 16 * (LDAT * 4) + nt * 16);
                mma16816(c[t], a, bf);
            }
        }
        const int r0 = mt * 16 + g;
        const int r1 = r0 + 8;
        const float i0 = 1.f / (psum[r0 * 4] + psum[r0 * 4 + 1]
                                + psum[r0 * 4 + 2] + psum[r0 * 4 + 3]);
        const float i1 = 1.f / (psum[r1 * 4] + psum[r1 * 4 + 1]
                                + psum[r1 * 4 + 2] + psum[r1 * 4 + 3]);
        #pragma unroll
        for (int t = 0; t < 2; t++) {
            const int col = (wn + t * 4) * 8 + 2 * t4;
            __half2 h0 = __floats2half2_rn(c[t][0] * i0, c[t][1] * i0);
            __half2 h1 = __floats2half2_rn(c[t][2] * i1, c[t][3] * i1);
            *(__half2*)(o + ((size_t)(b * SQ + q0 + r0)) * DIM + h * HDIM + col) = h0;
            *(__half2*)(o + ((size_t)(b * SQ + q0 + r1)) * DIM + h * HDIM + col) = h1;
        }
    }
}

// ---------------- query-0 global attention: split-softmax --------------------
__global__ __launch_bounds__(128)
void attn_g1_kernel(const __half* __restrict__ qkv,
                    const unsigned char* __restrict__ pad,
                    float* __restrict__ pm, float* __restrict__ ps,
                    float* __restrict__ pa) {
    const int h = blockIdx.x, b = blockIdx.y, c = blockIdx.z;
    const int tid = threadIdx.x;
    const int idx = (b * NH + h) * GCH + c;
    __shared__ float qf[HDIM];
    __shared__ float S2[128];
    __shared__ float red[128];

    if (tid < HDIM)
        qf[tid] = __half2float(qkv[((size_t)(b * SQ)) * QKVD + h * HDIM + tid]);
    __syncthreads();

    const int j = c * 128 + tid;
    {
        const __half2* kp = (const __half2*)(qkv + ((size_t)(b * SQ + j)) * QKVD
                                             + DIM + h * HDIM);
        float s = 0.f;
        #pragma unroll
        for (int i = 0; i < 32; i++) {
            float2 f = __half22float2(kp[i]);
            s += qf[2 * i] * f.x + qf[2 * i + 1] * f.y;
        }
        s *= 0.125f;
        if (pad[b * SQ + j]) s = -1e30f;
        S2[tid] = s;
        red[tid] = s;
    }
    __syncthreads();
    for (int st = 64; st > 0; st >>= 1) {
        if (tid < st) red[tid] = fmaxf(red[tid], red[tid + st]);
        __syncthreads();
    }
    const float mx = red[0];
    __syncthreads();
    {
        float e = __expf(S2[tid] - mx);
        S2[tid] = e;
        red[tid] = e;
    }
    __syncthreads();
    for (int st = 64; st > 0; st >>= 1) {
        if (tid < st) red[tid] += red[tid + st];
        __syncthreads();
    }
    if (tid == 0) { pm[idx] = mx; ps[idx] = red[0]; }
    __syncthreads();

    const int d = tid & 63, grp = tid >> 6;
    float acc = 0.f;
    for (int t = grp; t < 128; t += 2)
        acc += S2[t] * __half2float(qkv[((size_t)(b * SQ + c * 128 + t)) * QKVD
                                        + 2 * DIM + h * HDIM + d]);
    red[tid] = acc;
    __syncthreads();
    if (tid < HDIM)
        pa[(size_t)idx * HDIM + tid] = red[tid] + red[tid + 64];
}

__global__ __launch_bounds__(64)
void attn_g2_kernel(const float* __restrict__ pm, const float* __restrict__ ps,
                    const float* __restrict__ pa, __half* __restrict__ o) {
    const int h = blockIdx.x, b = blockIdx.y;
    const int d = threadIdx.x;
    const int base = (b * NH + h) * GCH;
    float M = -1e30f;
    #pragma unroll
    for (int c = 0; c < GCH; c++) M = fmaxf(M, pm[base + c]);
    float S = 0.f, acc = 0.f;
    #pragma unroll
    for (int c = 0; c < GCH; c++) {
        const float w = __expf(pm[base + c] - M);
        S   += ps[base + c] * w;
        acc += pa[(size_t)(base + c) * HDIM + d] * w;
    }
    o[((size_t)(b * SQ)) * DIM + h * HDIM + d] = __float2half(acc / S);
}

// ---------------- launch -----------------------------------------------------
extern "C" void kernel_launch(void* const* d_in, const int* in_sizes, int n_in,
                              void* d_out, int out_size) {
    const float* x   = (const float*)d_in[0];
    const unsigned char* pad = (const unsigned char*)d_in[1];
    const float* ipw = (const float*)d_in[3];
    const float* ipb = (const float*)d_in[4];
    const float* opw = (const float*)d_in[5];
    const float* opb = (const float*)d_in[6];
    const float* l1g = (const float*)d_in[7];
    const float* l1b = (const float*)d_in[8];
    const float* l2g = (const float*)d_in[9];
    const float* l2b = (const float*)d_in[10];
    const float* w1  = (const float*)d_in[11];
    const float* b1  = (const float*)d_in[12];
    const float* w2  = (const float*)d_in[13];
    const float* b2  = (const float*)d_in[14];
    float* out = (float*)d_out;

    __half *a, *qkvh, *o, *f, *hh, *wqkv, *wo, *w1h, *w2h;
    float *x1, *pm, *ps, *pa;
    cudaGetSymbolAddress((void**)&a,    g_a);
    cudaGetSymbolAddress((void**)&qkvh, g_qkvh);
    cudaGetSymbolAddress((void**)&o,    g_o);
    cudaGetSymbolAddress((void**)&x1,   g_x1);
    cudaGetSymbolAddress((void**)&f,    g_f);
    cudaGetSymbolAddress((void**)&hh,   g_h);
    cudaGetSymbolAddress((void**)&wqkv, g_wqkv);
    cudaGetSymbolAddress((void**)&wo,   g_wo);
    cudaGetSymbolAddress((void**)&w1h,  g_w1h);
    cudaGetSymbolAddress((void**)&w2h,  g_w2h);
    cudaGetSymbolAddress((void**)&pm,   g_pm);
    cudaGetSymbolAddress((void**)&ps,   g_ps);
    cudaGetSymbolAddress((void**)&pa,   g_pa);

    cudaFuncSetAttribute(attn_tile_kernel,
                         cudaFuncAttributeMaxDynamicSharedMemorySize, ATTN_SMEM);
    cudaFuncSetAttribute(tgemm<0, __half>,
                         cudaFuncAttributeMaxDynamicSharedMemorySize, GEMM_SMEM);
    cudaFuncSetAttribute(tgemm<1, __half>,
                         cudaFuncAttributeMaxDynamicSharedMemorySize, GEMM_SMEM);
    cudaFuncSetAttribute(tgemm<2, float>,
                         cudaFuncAttributeMaxDynamicSharedMemorySize, GEMM_SMEM);

    // fused weight conversion
    const int ntot = (N1 + N2 + N3 + N4) / 4;
    f2h_all_kernel<<<(ntot + 255) / 256, 256>>>(ipw, wqkv, opw, wo, w1, w1h, w2, w2h);

    // 1. pre-LN for attention -> half
    ln_kernel<<<MROWS / 2, 256>>>(x, l1g, l1b, a);
    // 2. QKV projection (fp16 MMA) -> half
    tgemm<0, __half><<<dim3(QKVD / 128, MROWS / 128), 256, GEMM_SMEM>>>(
        a, wqkv, ipb, nullptr, qkvh, MROWS, QKVD, DIM);
    // 3. attention: tiled local windows + q==0 global split-softmax fix-up
    attn_tile_kernel<<<dim3(SQ / TQ, NH, NB), 256, ATTN_SMEM>>>(qkvh, pad, o);
    attn_g1_kernel<<<dim3(NH, NB, GCH), 128>>>(qkvh, pad, pm, ps, pa);
    attn_g2_kernel<<<dim3(NH, NB), 64>>>(pm, ps, pa, o);
    // 4. out projection + residual(x fp32) -> x1 (fp32)
    tgemm<2, float><<<dim3(DIM / 128, MROWS / 128), 256, GEMM_SMEM>>>(
        o, wo, opb, x, x1, MROWS, DIM, DIM);
    // 5. pre-LN for FF -> half
    ln_kernel<<<MROWS / 2, 256>>>(x1, l2g, l2b, f);
    // 6. FF1 + exact GELU -> half
    tgemm<1, __half><<<dim3(FFD / 128, MROWS / 128), 256, GEMM_SMEM>>>(
        f, w1h, b1, nullptr, hh, MROWS, FFD, DIM);
    // 7. FF2 + residual(x1 fp32) -> final fp32 output
    tgemm<2, float><<<dim3(DIM / 128, MROWS / 128), 256, GEMM_SMEM>>>(
        hh, w2h, b2, x1, out, MROWS, DIM, FFD);
}

// round 17
// speedup vs baseline: 1.0673x; 1.0673x over previous
#include <cuda_runtime.h>
#include <cuda_fp16.h>
#include <math.h>
#include <stdint.h>

#define SQ   2048
#define DIM  512
#define NH   8
#define HDIM 64
#define NB   4
#define WIN  64
#define MROWS (NB * SQ)        // 8192
#define QKVD (3 * DIM)         // 1536
#define FFD  2048
#define GCH  16                // key chunks for query-0 global attention

// ---------------- scratch ----------------------------------------------------
__device__ __half g_a   [(size_t)MROWS * DIM];
__device__ __half g_qkvh[(size_t)MROWS * QKVD];
__device__ __half g_o   [(size_t)MROWS * DIM];
__device__ float  g_x1  [(size_t)MROWS * DIM];
__device__ __half g_f   [(size_t)MROWS * DIM];
__device__ __half g_h   [(size_t)MROWS * FFD];
__device__ __half g_wqkv[(size_t)QKVD * DIM];
__device__ __half g_wo  [(size_t)DIM * DIM];
__device__ __half g_w1h [(size_t)FFD * DIM];
__device__ __half g_w2h [(size_t)DIM * FFD];
// split-softmax partials for query-0 global attention
__device__ float  g_pm  [NB * NH * GCH];
__device__ float  g_ps  [NB * NH * GCH];
__device__ float  g_pa  [NB * NH * GCH * HDIM];

// ---------------- helpers ----------------------------------------------------
__device__ __forceinline__ uint32_t smem_u32(const void* p) {
    return (uint32_t)__cvta_generic_to_shared(p);
}
__device__ __forceinline__ void ldsm_x4(uint32_t* r, uint32_t addr) {
    asm volatile("ldmatrix.sync.aligned.m8n8.x4.shared.b16 {%0,%1,%2,%3}, [%4];\n"
        : "=r"(r[0]), "=r"(r[1]), "=r"(r[2]), "=r"(r[3]) : "r"(addr));
}
__device__ __forceinline__ void ldsm_x2(uint32_t* r, uint32_t addr) {
    asm volatile("ldmatrix.sync.aligned.m8n8.x2.shared.b16 {%0,%1}, [%2];\n"
        : "=r"(r[0]), "=r"(r[1]) : "r"(addr));
}
__device__ __forceinline__ void ldsm_x2_trans(uint32_t* r, uint32_t addr) {
    asm volatile("ldmatrix.sync.aligned.m8n8.x2.trans.shared.b16 {%0,%1}, [%2];\n"
        : "=r"(r[0]), "=r"(r[1]) : "r"(addr));
}
__device__ __forceinline__ void mma16816(float* c, const uint32_t* a, const uint32_t* b) {
    asm volatile(
        "mma.sync.aligned.m16n8k16.row.col.f32.f16.f16.f32 "
        "{%0,%1,%2,%3},{%4,%5,%6,%7},{%8,%9},{%0,%1,%2,%3};\n"
        : "+f"(c[0]), "+f"(c[1]), "+f"(c[2]), "+f"(c[3])
        : "r"(a[0]), "r"(a[1]), "r"(a[2]), "r"(a[3]), "r"(b[0]), "r"(b[1]));
}
__device__ __forceinline__ void cp16cg(uint32_t saddr, const void* g) {
    asm volatile("cp.async.cg.shared.global [%0], [%1], 16;\n" :: "r"(saddr), "l"(g));
}
#define CP_COMMIT() asm volatile("cp.async.commit_group;\n" ::: "memory")
#define CP_WAIT1()  asm volatile("cp.async.wait_group 1;\n" ::: "memory")
#define CP_WAIT0()  asm volatile("cp.async.wait_group 0;\n" ::: "memory")

__device__ __forceinline__ float gelu_exact(float v) {
    return 0.5f * v * (1.0f + erff(v * 0.70710678118654752f));
}
__device__ __forceinline__ void st2(float* p, float a, float b) { p[0] = a; p[1] = b; }
__device__ __forceinline__ void st2(__half* p, float a, float b) {
    *(__half2*)p = __floats2half2_rn(a, b);
}

// ---------------- fused fp32 -> fp16 weight convert --------------------------
#define N1 (QKVD * DIM)
#define N2 (DIM * DIM)
#define N3 (FFD * DIM)
#define N4 (DIM * FFD)
__global__ void f2h_all_kernel(const float* __restrict__ s1, __half* __restrict__ d1,
                               const float* __restrict__ s2, __half* __restrict__ d2,
                               const float* __restrict__ s3, __half* __restrict__ d3,
                               const float* __restrict__ s4, __half* __restrict__ d4) {
    int i = (blockIdx.x * blockDim.x + threadIdx.x) * 4;
    const float* s; __half* d;
    if (i < N1)                     { s = s1; d = d1; }
    else if ((i -= N1) < N2)        { s = s2; d = d2; }
    else if ((i -= N2) < N3)        { s = s3; d = d3; }
    else if ((i -= N3) < N4)        { s = s4; d = d4; }
    else return;
    float4 v = *(const float4*)(s + i);
    ((__half2*)d)[i / 2]     = __floats2half2_rn(v.x, v.y);
    ((__half2*)d)[i / 2 + 1] = __floats2half2_rn(v.z, v.w);
}

// ---------------- LayerNorm: 2 rows per 256-thread block ---------------------
__global__ __launch_bounds__(256)
void ln_kernel(const float* __restrict__ x, const float* __restrict__ g,
               const float* __restrict__ bb, __half* __restrict__ out) {
    const int half = threadIdx.x >> 7;
    const int tid  = threadIdx.x & 127;
    const int row  = blockIdx.x * 2 + half;
    const float4* xr = (const float4*)(x + (size_t)row * DIM);
    float4 v = xr[tid];
    float s  = v.x + v.y + v.z + v.w;
    float ss = v.x*v.x + v.y*v.y + v.z*v.z + v.w*v.w;
    #pragma unroll
    for (int o = 16; o > 0; o >>= 1) {
        s  += __shfl_xor_sync(0xffffffffu, s,  o);
        ss += __shfl_xor_sync(0xffffffffu, ss, o);
    }
    __shared__ float as_[2][4], ass_[2][4];
    if ((tid & 31) == 0) { as_[half][tid >> 5] = s; ass_[half][tid >> 5] = ss; }
    __syncthreads();
    s  = as_[half][0] + as_[half][1] + as_[half][2] + as_[half][3];
    ss = ass_[half][0] + ass_[half][1] + ass_[half][2] + ass_[half][3];
    const float mean = s * (1.0f / DIM);
    const float var  = ss * (1.0f / DIM) - mean * mean;
    const float inv  = rsqrtf(var + 1e-5f);
    float4 gv = ((const float4*)g)[tid];
    float4 bv = ((const float4*)bb)[tid];
    float r0 = (v.x - mean) * inv * gv.x + bv.x;
    float r1 = (v.y - mean) * inv * gv.y + bv.y;
    float r2 = (v.z - mean) * inv * gv.z + bv.z;
    float r3 = (v.w - mean) * inv * gv.w + bv.w;
    __half2* orow = (__half2*)(out + (size_t)row * DIM);
    orow[2 * tid]     = __floats2half2_rn(r0, r1);
    orow[2 * tid + 1] = __floats2half2_rn(r2, r3);
}

// ---------------- fp16 tensor-core GEMM: 3-stage pipeline (R15 proven) -------
#define LDK 20           // smem words (half2) per 32-half row (16 + pad 4)
#define STGW (128 * LDK) // words per stage per operand
#define GEMM_SMEM (6 * STGW * 4)  // 3 stages x (A + B) = 61.4 KB

template <int EPI, typename OT>
__global__ __launch_bounds__(256)
void tgemm(const __half* __restrict__ A, const __half* __restrict__ W,
           const float* __restrict__ bias, const float* __restrict__ R,
           OT* __restrict__ C, int M, int N, int K) {
    extern __shared__ __align__(16) uint32_t dynsm[];
    uint32_t* As = dynsm;              // 3 * STGW
    uint32_t* Bs = dynsm + 3 * STGW;   // 3 * STGW

    const int tid  = threadIdx.x;
    const int warp = tid >> 5;
    const int lane = tid & 31;
    const int g    = lane >> 2;
    const int t4   = lane & 3;
    const int wm   = warp >> 2;
    const int wn   = warp & 3;

    const int bm = blockIdx.y * 128;
    const int bn = blockIdx.x * 128;

    const int lrow = tid >> 1;
    const __half* gA = A + (size_t)(bm + lrow) * K + (tid & 1) * 16;
    const __half* gB = W + (size_t)(bn + lrow) * K + (tid & 1) * 16;
    const uint32_t sA = smem_u32(As) + (lrow * LDK + (tid & 1) * 8) * 4;
    const uint32_t sB = smem_u32(Bs) + (lrow * LDK + (tid & 1) * 8) * 4;
    const int STGB = STGW * 4;         // stage stride in bytes

    const int l15 = lane & 15;
    const uint32_t aBase = smem_u32(As) +
        (((wm * 64 + l15) * LDK) + (lane >> 4) * 4) * 4;
    // paired-B ldsm.x4 base (R14 proven)
    const uint32_t bBase4 = smem_u32(Bs) +
        (((wn * 32 + (lane & 7)) * LDK) + ((lane >> 3) & 1) * 4) * 4
        + (lane >> 4) * (8 * LDK * 4);

    float acc[4][4][4];
    #pragma unroll
    for (int i = 0; i < 4; i++)
        #pragma unroll
        for (int j = 0; j < 4; j++)
            #pragma unroll
            for (int v = 0; v < 4; v++) acc[i][j][v] = 0.0f;

    const int NT = K / 32;
    // prologue: stages 0 and 1
    cp16cg(sA, gA); cp16cg(sA + 16, gA + 8);
    cp16cg(sB, gB); cp16cg(sB + 16, gB + 8);
    CP_COMMIT();
    cp16cg(sA + STGB, gA + 32); cp16cg(sA + STGB + 16, gA + 40);
    cp16cg(sB + STGB, gB + 32); cp16cg(sB + STGB + 16, gB + 40);
    CP_COMMIT();

    int cs = 0;      // compute stage
    int pf = 2;      // prefetch stage
    for (int t = 0; t < NT; t++) {
        CP_WAIT1();
        __syncthreads();
        if (t + 2 < NT) {
            const int k0 = (t + 2) * 32;
            const int po = pf * STGB;
            cp16cg(sA + po, gA + k0); cp16cg(sA + po + 16, gA + k0 + 8);
            cp16cg(sB + po, gB + k0); cp16cg(sB + po + 16, gB + k0 + 8);
        }
        CP_COMMIT();
        const int sb = cs * STGB;
        #pragma unroll
        for (int kk = 0; kk < 2; kk++) {
            uint32_t af[4][4], bf[4][2];
            #pragma unroll
            for (int mt = 0; mt < 4; mt++)
                ldsm_x4(af[mt], aBase + sb + mt * (16 * LDK * 4) + kk * 32);
            // two x4 loads cover n-tiles {0,1} and {2,3}
            ldsm_x4(&bf[0][0], bBase4 + sb + kk * 32);
            ldsm_x4(&bf[2][0], bBase4 + sb + 16 * LDK * 4 + kk * 32);
            #pragma unroll
            for (int mt = 0; mt < 4; mt++)
                #pragma unroll
                for (int nt = 0; nt < 4; nt++)
                    mma16816(acc[mt][nt], af[mt], bf[nt]);
        }
        cs = (cs == 2) ? 0 : cs + 1;
        pf = (pf == 2) ? 0 : pf + 1;
    }

    #pragma unroll
    for (int mt = 0; mt < 4; mt++) {
        const int r0 = bm + wm * 64 + mt * 16 + g;
        const int r1 = r0 + 8;
        #pragma unroll
        for (int nt = 0; nt < 4; nt++) {
            const int col = bn + wn * 32 + nt * 8 + 2 * t4;
            const float b0 = bias[col], b1 = bias[col + 1];
            float v0 = acc[mt][nt][0] + b0;
            float v1 = acc[mt][nt][1] + b1;
            float v2 = acc[mt][nt][2] + b0;
            float v3 = acc[mt][nt][3] + b1;
            if (EPI == 1) {
                v0 = gelu_exact(v0); v1 = gelu_exact(v1);
                v2 = gelu_exact(v2); v3 = gelu_exact(v3);
            }
            if (EPI == 2) {
                float2 ra = *(const float2*)(R + (size_t)r0 * N + col);
                float2 rb = *(const float2*)(R + (size_t)r1 * N + col);
                v0 += ra.x; v1 += ra.y; v2 += rb.x; v3 += rb.y;
            }
            st2(C + (size_t)r0 * N + col, v0, v1);
            st2(C + (size_t)r1 * N + col, v2, v3);
        }
    }
}

// ---------------- Tiled attention (R15 proven, unchanged) --------------------
#define TQ    32
#define NKP   168
#define VROWS 176
#define LDAT  36
#define LDP   184
#define KJ_INVALID 0x40000000
#define ATTN_SMEM (((32 + NKP + VROWS) * LDAT) * 4 + 32 * LDP * 2 + 2 * 128 * 4 + NKP * 4 + 64)

__global__ __launch_bounds__(256)
void attn_tile_kernel(const __half* __restrict__ qkv,
                      const unsigned char* __restrict__ pad,
                      __half* __restrict__ o) {
    extern __shared__ __align__(16) uint32_t sm[];
    uint32_t* Qs  = sm;
    uint32_t* Ksm = Qs + 32 * LDAT;
    uint32_t* Vsm = Ksm + NKP * LDAT;
    __half*   Ps  = (__half*)(Vsm + VROWS * LDAT);
    float*    pmax = (float*)(Ps + 32 * LDP);
    float*    psum = pmax + 128;
    int*      kjs  = (int*)(psum + 128);

    const int q0 = blockIdx.x * TQ;
    const int h  = blockIdx.y;
    const int b  = blockIdx.z;
    const int tid  = threadIdx.x;
    const int warp = tid >> 5;
    const int lane = tid & 31;
    const int g    = lane >> 2;
    const int t4   = lane & 3;

    int ks = q0 - WIN; if (ks < 0) ks = 0;
    int ke = q0 + TQ - 1 + WIN; if (ke > SQ - 1) ke = SQ - 1;
    const int hasg = (ks > 0) ? 1 : 0;
    const int nk = ke - ks + 1 + hasg;
    const int ntmax = (nk + 7) >> 3;
    const int NTK = (nk + 15) >> 4;

    {
        const int qrow = tid >> 3, l8 = tid & 7;
        cp16cg(smem_u32(Qs) + (qrow * LDAT + l8 * 4) * 4,
               qkv + ((size_t)(b * SQ + q0 + qrow)) * QKVD + h * HDIM + l8 * 8);
    }
    {
        const int l8 = tid & 7;
        for (int j = tid >> 3; j < VROWS; j += 32) {
            if (j < nk) {
                const int kj = (hasg && j == 0) ? 0 : ks + j - hasg;
                const __half* base = qkv + ((size_t)(b * SQ + kj)) * QKVD;
                cp16cg(smem_u32(Ksm) + (j * LDAT + l8 * 4) * 4,
                       base + DIM + h * HDIM + l8 * 8);
                cp16cg(smem_u32(Vsm) + (j * LDAT + l8 * 4) * 4,
                       base + 2 * DIM + h * HDIM + l8 * 8);
                if (l8 == 0) kjs[j] = pad[b * SQ + kj] ? KJ_INVALID : kj;
            } else {
                uint4 z = {0u, 0u, 0u, 0u};
                *(uint4*)(Vsm + j * LDAT + l8 * 4) = z;
                if (l8 == 0 && j < NKP) kjs[j] = KJ_INVALID;
            }
        }
    }
    {
        const int row = tid >> 3;
        const int cc = ntmax * 8 + (tid & 7);
        if (cc < NTK * 16) Ps[row * LDP + cc] = __float2half(0.f);
    }
    CP_COMMIT();
    CP_WAIT0();
    __syncthreads();

    {
        const int mt = warp & 1;
        const int ng = warp >> 1;
        const int l15 = lane & 15;
        const uint32_t aAddr = smem_u32(Qs) +
            (((mt * 16 + l15) * LDAT) + (lane >> 4) * 4) * 4;
        uint32_t af[4][4];
        #pragma unroll
        for (int kk = 0; kk < 4; kk++) ldsm_x4(af[kk], aAddr + kk * 32);

        const uint32_t bAddr = smem_u32(Ksm) +
            (((l15 & 7) * LDAT) + (l15 >> 3) * 4) * 4;

        float cs[6][4];
        #pragma unroll
        for (int i = 0; i < 6; i++) {
            const int nt = ng + i * 4;
            cs[i][0] = cs[i][1] = cs[i][2] = cs[i][3] = 0.f;
            if (nt < ntmax) {
                #pragma unroll
                for (int kk = 0; kk < 4; kk++) {
                    uint32_t bf[2];
                    ldsm_x2(bf, bAddr + nt * (8 * LDAT * 4) + kk * 32);
                    mma16816(cs[i], af[kk], bf);
                }
            }
        }

        const int qg0 = q0 + mt * 16 + g;
        const int qg1 = qg0 + 8;
        float m0 = -1e30f, m1 = -1e30f;
        #pragma unroll
        for (int i = 0; i < 6; i++) {
            const int nt = ng + i * 4;
            if (nt < ntmax) {
                #pragma unroll
                for (int u = 0; u < 2; u++) {
                    const int col = nt * 8 + 2 * t4 + u;
                    const int kj = kjs[col];
                    const int d0 = kj - qg0;
                    const bool v0 = (kj == 0) || (d0 >= -WIN && d0 <= WIN);
                    float s0 = v0 ? cs[i][u] * 0.125f : -1e30f;
                    cs[i][u] = s0; m0 = fmaxf(m0, s0);
                    const int d1 = kj - qg1;
                    const bool v1 = (kj == 0) || (d1 >= -WIN && d1 <= WIN);
                    float s1 = v1 ? cs[i][u + 2] * 0.125f : -1e30f;
                    cs[i][u + 2] = s1; m1 = fmaxf(m1, s1);
                }
            }
        }
        m0 = fmaxf(m0, __shfl_xor_sync(0xffffffffu, m0, 1));
        m0 = fmaxf(m0, __shfl_xor_sync(0xffffffffu, m0, 2));
        m1 = fmaxf(m1, __shfl_xor_sync(0xffffffffu, m1, 1));
        m1 = fmaxf(m1, __shfl_xor_sync(0xffffffffu, m1, 2));
        const int r0 = mt * 16 + g, r1 = r0 + 8;
        if (t4 == 0) { pmax[r0 * 4 + ng] = m0; pmax[r1 * 4 + ng] = m1; }
        __syncthreads();
        const float M0 = fmaxf(fmaxf(pmax[r0 * 4], pmax[r0 * 4 + 1]),
                               fmaxf(pmax[r0 * 4 + 2], pmax[r0 * 4 + 3]));
        const float M1 = fmaxf(fmaxf(pmax[r1 * 4], pmax[r1 * 4 + 1]),
                               fmaxf(pmax[r1 * 4 + 2], pmax[r1 * 4 + 3]));

        float s0 = 0.f, s1 = 0.f;
        #pragma unroll
        for (int i = 0; i < 6; i++) {
            const int nt = ng + i * 4;
            if (nt < ntmax) {
                const int col = nt * 8 + 2 * t4;
                float e0 = __expf(cs[i][0] - M0);
                float e1 = __expf(cs[i][1] - M0);
                float e2 = __expf(cs[i][2] - M1);
                float e3 = __expf(cs[i][3] - M1);
                s0 += e0 + e1; s1 += e2 + e3;
                *(__half2*)(Ps + r0 * LDP + col) = __floats2half2_rn(e0, e1);
                *(__half2*)(Ps + r1 * LDP + col) = __floats2half2_rn(e2, e3);
            }
        }
        s0 += __shfl_xor_sync(0xffffffffu, s0, 1);
        s0 += __shfl_xor_sync(0xffffffffu, s0, 2);
        s1 += __shfl_xor_sync(0xffffffffu, s1, 1);
        s1 += __shfl_xor_sync(0xffffffffu, s1, 2);
        if (t4 == 0) { psum[r0 * 4 + ng] = s0; psum[r1 * 4 + ng] = s1; }
    }
    __syncthreads();

    {
        const int mt = warp >> 2;
        const int wn = warp & 3;
        const int l15 = lane & 15;
        float c[2][4];
        #pragma unroll
        for (int t = 0; t < 2; t++)
            #pragma unroll
            for (int v = 0; v < 4; v++) c[t][v] = 0.f;

        const uint32_t aBase = smem_u32(Ps) +
            (mt * 16 + l15) * (LDP * 2) + (lane >> 4) * 16;
        const uint32_t vBase = smem_u32(Vsm) + l15 * (LDAT * 4);
        for (int kk = 0; kk < NTK; kk++) {
            uint32_t a[4];
            ldsm_x4(a, aBase + kk * 32);
            #pragma unroll
            for (int t = 0; t < 2; t++) {
                const int nt = wn + t * 4;
                uint32_t bf[2];
                ldsm_x2_trans(bf, vBase + kk * 16 * (LDAT * 4) + nt * 16);
                mma16816(c[t], a, bf);
            }
        }
        const int r0 = mt * 16 + g;
        const int r1 = r0 + 8;
        const float i0 = 1.f / (psum[r0 * 4] + psum[r0 * 4 + 1]
                                + psum[r0 * 4 + 2] + psum[r0 * 4 + 3]);
        const float i1 = 1.f / (psum[r1 * 4] + psum[r1 * 4 + 1]
                                + psum[r1 * 4 + 2] + psum[r1 * 4 + 3]);
        #pragma unroll
        for (int t = 0; t < 2; t++) {
            const int col = (wn + t * 4) * 8 + 2 * t4;
            __half2 h0 = __floats2half2_rn(c[t][0] * i0, c[t][1] * i0);
            __half2 h1 = __floats2half2_rn(c[t][2] * i1, c[t][3] * i1);
            *(__half2*)(o + ((size_t)(b * SQ + q0 + r0)) * DIM + h * HDIM + col) = h0;
            *(__half2*)(o + ((size_t)(b * SQ + q0 + r1)) * DIM + h * HDIM + col) = h1;
        }
    }
}

// ---------------- query-0 global attention: split-softmax --------------------
__global__ __launch_bounds__(128)
void attn_g1_kernel(const __half* __restrict__ qkv,
                    const unsigned char* __restrict__ pad,
                    float* __restrict__ pm, float* __restrict__ ps,
                    float* __restrict__ pa) {
    const int h = blockIdx.x, b = blockIdx.y, c = blockIdx.z;
    const int tid = threadIdx.x;
    const int idx = (b * NH + h) * GCH + c;
    __shared__ float qf[HDIM];
    __shared__ float S2[128];
    __shared__ float red[128];

    if (tid < HDIM)
        qf[tid] = __half2float(qkv[((size_t)(b * SQ)) * QKVD + h * HDIM + tid]);
    __syncthreads();

    const int j = c * 128 + tid;
    {
        const __half2* kp = (const __half2*)(qkv + ((size_t)(b * SQ + j)) * QKVD
                                             + DIM + h * HDIM);
        float s = 0.f;
        #pragma unroll
        for (int i = 0; i < 32; i++) {
            float2 f = __half22float2(kp[i]);
            s += qf[2 * i] * f.x + qf[2 * i + 1] * f.y;
        }
        s *= 0.125f;
        if (pad[b * SQ + j]) s = -1e30f;
        S2[tid] = s;
        red[tid] = s;
    }
    __syncthreads();
    for (int st = 64; st > 0; st >>= 1) {
        if (tid < st) red[tid] = fmaxf(red[tid], red[tid + st]);
        __syncthreads();
    }
    const float mx = red[0];
    __syncthreads();
    {
        float e = __expf(S2[tid] - mx);
        S2[tid] = e;
        red[tid] = e;
    }
    __syncthreads();
    for (int st = 64; st > 0; st >>= 1) {
        if (tid < st) red[tid] += red[tid + st];
        __syncthreads();
    }
    if (tid == 0) { pm[idx] = mx; ps[idx] = red[0]; }
    __syncthreads();

    const int d = tid & 63, grp = tid >> 6;
    float acc = 0.f;
    for (int t = grp; t < 128; t += 2)
        acc += S2[t] * __half2float(qkv[((size_t)(b * SQ + c * 128 + t)) * QKVD
                                        + 2 * DIM + h * HDIM + d]);
    red[tid] = acc;
    __syncthreads();
    if (tid < HDIM)
        pa[(size_t)idx * HDIM + tid] = red[tid] + red[tid + 64];
}

__global__ __launch_bounds__(64)
void attn_g2_kernel(const float* __restrict__ pm, const float* __restrict__ ps,
                    const float* __restrict__ pa, __half* __restrict__ o) {
    const int h = blockIdx.x, b = blockIdx.y;
    const int d = threadIdx.x;
    const int base = (b * NH + h) * GCH;
    float M = -1e30f;
    #pragma unroll
    for (int c = 0; c < GCH; c++) M = fmaxf(M, pm[base + c]);
    float S = 0.f, acc = 0.f;
    #pragma unroll
    for (int c = 0; c < GCH; c++) {
        const float w = __expf(pm[base + c] - M);
        S   += ps[base + c] * w;
        acc += pa[(size_t)(base + c) * HDIM + d] * w;
    }
    o[((size_t)(b * SQ)) * DIM + h * HDIM + d] = __float2half(acc / S);
}

// ---------------- launch -----------------------------------------------------
extern "C" void kernel_launch(void* const* d_in, const int* in_sizes, int n_in,
                              void* d_out, int out_size) {
    const float* x   = (const float*)d_in[0];
    const unsigned char* pad = (const unsigned char*)d_in[1];
    const float* ipw = (const float*)d_in[3];
    const float* ipb = (const float*)d_in[4];
    const float* opw = (const float*)d_in[5];
    const float* opb = (const float*)d_in[6];
    const float* l1g = (const float*)d_in[7];
    const float* l1b = (const float*)d_in[8];
    const float* l2g = (const float*)d_in[9];
    const float* l2b = (const float*)d_in[10];
    const float* w1  = (const float*)d_in[11];
    const float* b1  = (const float*)d_in[12];
    const float* w2  = (const float*)d_in[13];
    const float* b2  = (const float*)d_in[14];
    float* out = (float*)d_out;

    __half *a, *qkvh, *o, *f, *hh, *wqkv, *wo, *w1h, *w2h;
    float *x1, *pm, *ps, *pa;
    cudaGetSymbolAddress((void**)&a,    g_a);
    cudaGetSymbolAddress((void**)&qkvh, g_qkvh);
    cudaGetSymbolAddress((void**)&o,    g_o);
    cudaGetSymbolAddress((void**)&x1,   g_x1);
    cudaGetSymbolAddress((void**)&f,    g_f);
    cudaGetSymbolAddress((void**)&hh,   g_h);
    cudaGetSymbolAddress((void**)&wqkv, g_wqkv);
    cudaGetSymbolAddress((void**)&wo,   g_wo);
    cudaGetSymbolAddress((void**)&w1h,  g_w1h);
    cudaGetSymbolAddress((void**)&w2h,  g_w2h);
    cudaGetSymbolAddress((void**)&pm,   g_pm);
    cudaGetSymbolAddress((void**)&ps,   g_ps);
    cudaGetSymbolAddress((void**)&pa,   g_pa);

    cudaFuncSetAttribute(attn_tile_kernel,
                         cudaFuncAttributeMaxDynamicSharedMemorySize, ATTN_SMEM);
    cudaFuncSetAttribute(tgemm<0, __half>,
                         cudaFuncAttributeMaxDynamicSharedMemorySize, GEMM_SMEM);
    cudaFuncSetAttribute(tgemm<1, __half>,
                         cudaFuncAttributeMaxDynamicSharedMemorySize, GEMM_SMEM);
    cudaFuncSetAttribute(tgemm<2, float>,
                         cudaFuncAttributeMaxDynamicSharedMemorySize, GEMM_SMEM);

    // fused weight conversion
    const int ntot = (N1 + N2 + N3 + N4) / 4;
    f2h_all_kernel<<<(ntot + 255) / 256, 256>>>(ipw, wqkv, opw, wo, w1, w1h, w2, w2h);

    // 1. pre-LN for attention -> half
    ln_kernel<<<MROWS / 2, 256>>>(x, l1g, l1b, a);
    // 2. QKV projection (fp16 MMA) -> half
    tgemm<0, __half><<<dim3(QKVD / 128, MROWS / 128), 256, GEMM_SMEM>>>(
        a, wqkv, ipb, nullptr, qkvh, MROWS, QKVD, DIM);
    // 3. attention: tiled local windows + q==0 global split-softmax fix-up
    attn_tile_kernel<<<dim3(SQ / TQ, NH, NB), 256, ATTN_SMEM>>>(qkvh, pad, o);
    attn_g1_kernel<<<dim3(NH, NB, GCH), 128>>>(qkvh, pad, pm, ps, pa);
    attn_g2_kernel<<<dim3(NH, NB), 64>>>(pm, ps, pa, o);
    // 4. out projection + residual(x fp32) -> x1 (fp32)
    tgemm<2, float><<<dim3(DIM / 128, MROWS / 128), 256, GEMM_SMEM>>>(
        o, wo, opb, x, x1, MROWS, DIM, DIM);
    // 5. pre-LN for FF -> half
    ln_kernel<<<MROWS / 2, 256>>>(x1, l2g, l2b, f);
    // 6. FF1 + exact GELU -> half
    tgemm<1, __half><<<dim3(FFD / 128, MROWS / 128), 256, GEMM_SMEM>>>(
        f, w1h, b1, nullptr, hh, MROWS, FFD, DIM);
    // 7. FF2 + residual(x1 fp32) -> final fp32 output
    tgemm<2, float><<<dim3(DIM / 128, MROWS / 128), 256, GEMM_SMEM>>>(
        hh, w2h, b2, x1, out, MROWS, DIM, FFD);
}